// round 3
// baseline (speedup 1.0000x reference)
#include <cuda_runtime.h>
#include <cstddef>

// ---------------------------------------------------------------------------
// DWReg2DDecode3D: grid_sample -> upsample GEMM -> 4x(pool -> spiral dsconv
// -> relu) -> head dsconv.  B=16, NV={12544,6272,3136,1568,784}, SPIRAL=9.
// ---------------------------------------------------------------------------

#define B 16
#define SP 9

// scratch (device globals; no allocations allowed)
__device__ float g_gs[B * 64 * 256];          // grid-sampled feats (b,p,c)
__device__ float g_bufB[12845056];            // conv outputs       (max 16*3136*256)
__device__ float g_bufA[25690112];            // pool outputs       (max 16*6272*256)

// ---------------- packed f32x2 helpers (sm_10x FFMA2 path) -----------------
__device__ __forceinline__ void fma2(unsigned long long& d,
                                     unsigned long long a,
                                     unsigned long long b) {
    asm("fma.rn.f32x2 %0, %1, %2, %0;" : "+l"(d) : "l"(a), "l"(b));
}
__device__ __forceinline__ unsigned long long dup2(float x) {
    unsigned long long u;
    asm("mov.b64 %0, {%1, %1};" : "=l"(u) : "f"(x));
    return u;
}
__device__ __forceinline__ float2 unpk(unsigned long long u) {
    float2 r;
    asm("mov.b64 {%0, %1}, %2;" : "=f"(r.x), "=f"(r.y) : "l"(u));
    return r;
}

// ---------------- grid sample (bilinear, align_corners, zero pad) ----------
__global__ void __launch_bounds__(256)
k_gridsample(const float* __restrict__ uv, const float* __restrict__ feat,
             float* __restrict__ gs)
{
    const int b = blockIdx.x, c = threadIdx.x;
    const float* fb = feat + ((size_t)b * 256 + c) * 16;
    for (int p = 0; p < 64; ++p) {
        float gx = (uv[((size_t)b * 64 + p) * 2 + 0] - 0.5f) * 2.f;
        float gy = (uv[((size_t)b * 64 + p) * 2 + 1] - 0.5f) * 2.f;
        gx = fminf(fmaxf(gx, -1.f), 1.f);
        gy = fminf(fmaxf(gy, -1.f), 1.f);
        float x = (gx + 1.f) * 0.5f * 3.f;
        float y = (gy + 1.f) * 0.5f * 3.f;
        float x0f = floorf(x), y0f = floorf(y);
        int x0 = (int)x0f, y0 = (int)y0f;
        int x1 = x0 + 1, y1 = y0 + 1;
        float fx = x - x0f, fy = y - y0f;
        float wa = (1.f - fx) * (1.f - fy);
        float wb = (1.f - fx) * fy;
        float wc = fx * (1.f - fy);
        float wd = fx * fy;
        float Ia = (x0 >= 0 && x0 < 4 && y0 >= 0 && y0 < 4) ? fb[y0 * 4 + x0] : 0.f;
        float Ib = (x0 >= 0 && x0 < 4 && y1 >= 0 && y1 < 4) ? fb[y1 * 4 + x0] : 0.f;
        float Ic = (x1 >= 0 && x1 < 4 && y0 >= 0 && y0 < 4) ? fb[y0 * 4 + x1] : 0.f;
        float Id = (x1 >= 0 && x1 < 4 && y1 >= 0 && y1 < 4) ? fb[y1 * 4 + x1] : 0.f;
        gs[((size_t)b * 64 + p) * 256 + c] = Ia * wa + Ib * wb + Ic * wc + Id * wd;
    }
}

// ---------------- upsample GEMM: out[b,v,c] = sum_p up[v,p]*gs[b,p,c] ------
__global__ void __launch_bounds__(256)
k_upsample(const float* __restrict__ up, const float* __restrict__ gs,
           float* __restrict__ out)
{
    constexpr int VT = 16;
    __shared__ float up_s[VT][64];
    const int b = blockIdx.y, v0 = blockIdx.x * VT, c = threadIdx.x;
    for (int t = threadIdx.x; t < VT * 64; t += 256)
        up_s[t / 64][t % 64] = up[(size_t)(v0 + t / 64) * 64 + (t % 64)];
    __syncthreads();
    float acc[VT];
#pragma unroll
    for (int i = 0; i < VT; ++i) acc[i] = 0.f;
    for (int p = 0; p < 64; ++p) {
        float g = gs[((size_t)b * 64 + p) * 256 + c];
#pragma unroll
        for (int i = 0; i < VT; ++i) acc[i] = fmaf(up_s[i][p], g, acc[i]);
    }
#pragma unroll
    for (int i = 0; i < VT; ++i)
        out[((size_t)b * 784 + v0 + i) * 256 + c] = acc[i];
}

// ---------------- mesh up-pool: out[b,n,c] = sum_k x[b,col[3n+k],c]*val ----
template <int Ci>
__global__ void __launch_bounds__(256)
k_pool(const float4* __restrict__ x, const int* __restrict__ col,
       const float* __restrict__ val, float4* __restrict__ out,
       int Nin, int Nout)
{
    constexpr int CQ = Ci / 4;
    constexpr int VPB = 256 / CQ;
    const int b = blockIdx.y;
    const int n = blockIdx.x * VPB + threadIdx.x / CQ;
    const int cq = threadIdx.x % CQ;
    if (n >= Nout) return;
    const int c0 = col[3 * n + 0], c1 = col[3 * n + 1], c2 = col[3 * n + 2];
    const float v0 = val[3 * n + 0], v1 = val[3 * n + 1], v2 = val[3 * n + 2];
    const float4* xb = x + (size_t)b * Nin * CQ;
    float4 a = xb[(size_t)c0 * CQ + cq];
    float4 bb = xb[(size_t)c1 * CQ + cq];
    float4 cc = xb[(size_t)c2 * CQ + cq];
    float4 r;
    r.x = a.x * v0 + bb.x * v1 + cc.x * v2;
    r.y = a.y * v0 + bb.y * v1 + cc.y * v2;
    r.z = a.z * v0 + bb.z * v1 + cc.z * v2;
    r.w = a.w * v0 + bb.w * v1 + cc.w * v2;
    out[((size_t)b * Nout + n) * CQ + cq] = r;
}

// ---------------- fused spiral dsconv: gather*dw then @pw (+relu) ----------
// Phase A: y_s[v][ci] = sum_s x[idx[v,s], ci]*dw[ci,s]  (smem, 1 barrier)
// Phase B: out = y_s @ pw.  pw streamed via __ldg (L1-cached, no smem tile,
// no in-loop barriers).  Packed f32x2 accumulators over co.
template <int Ci, int Co, int VT, int CO_PT, bool RELU>
__global__ void __launch_bounds__(256)
k_dsconv(const float* __restrict__ x, const int* __restrict__ idx,
         const float* __restrict__ dw, const float* __restrict__ pw,
         float* __restrict__ out, int N)
{
    constexpr int CO_T = Co / CO_PT;       // threads along co
    constexpr int V_T = 256 / CO_T;        // threads along v
    constexpr int VPT = VT / V_T;          // v per thread
    constexpr int NU = CO_PT / 2;          // f32x2 accs per v
    static_assert(VPT >= 1 && VT % V_T == 0, "tile mismatch");

    __shared__ float y_s[VT][Ci];
    __shared__ int idx_s[VT * SP];

    const int b = blockIdx.y;
    const int n0 = blockIdx.x * VT;
    const int tid = threadIdx.x;

    for (int t = tid; t < VT * SP; t += 256)
        idx_s[t] = idx[(size_t)(n0 + t / SP) * SP + (t % SP)];
    __syncthreads();

    // ---- phase A ----
    {
        constexpr int CREP = 256 / Ci;
        constexpr int VCH = VT / CREP;
        const int ci = tid % Ci;
        const int vlo = (tid / Ci) * VCH;
        float dwr[SP];
#pragma unroll
        for (int s = 0; s < SP; ++s) dwr[s] = __ldg(&dw[(size_t)ci * SP + s]);
        const float* xb = x + ((size_t)b * N) * Ci + ci;
#pragma unroll 2
        for (int v = vlo; v < vlo + VCH; ++v) {
            float acc = 0.f;
#pragma unroll
            for (int s = 0; s < SP; ++s)
                acc = fmaf(xb[(size_t)idx_s[v * SP + s] * Ci], dwr[s], acc);
            y_s[v][ci] = acc;
        }
    }
    __syncthreads();

    // ---- phase B ----
    const int co_t = tid % CO_T;
    const int v_t = tid / CO_T;
    const int co0 = co_t * CO_PT;

    unsigned long long acc[VPT][NU];
#pragma unroll
    for (int i = 0; i < VPT; ++i)
#pragma unroll
        for (int u = 0; u < NU; ++u) acc[i][u] = 0ull;

    const float* pwb = pw + co0;
#pragma unroll 4
    for (int k = 0; k < Ci; k += 2) {
        // pw rows k, k+1 for this thread's co slice (L1-resident)
        unsigned long long p0[NU], p1[NU];
#pragma unroll
        for (int u = 0; u < NU; u += 2) {
            ulonglong2 q0 = __ldg(reinterpret_cast<const ulonglong2*>(
                pwb + (size_t)k * Co) + (u >> 1));
            ulonglong2 q1 = __ldg(reinterpret_cast<const ulonglong2*>(
                pwb + (size_t)(k + 1) * Co) + (u >> 1));
            p0[u] = q0.x; p0[u + 1] = q0.y;
            p1[u] = q1.x; p1[u + 1] = q1.y;
        }
#pragma unroll
        for (int vi = 0; vi < VPT; ++vi) {
            const float2 y2 =
                *reinterpret_cast<const float2*>(&y_s[v_t * VPT + vi][k]);
            const unsigned long long ya = dup2(y2.x);
            const unsigned long long yb = dup2(y2.y);
#pragma unroll
            for (int u = 0; u < NU; ++u) {
                fma2(acc[vi][u], ya, p0[u]);
                fma2(acc[vi][u], yb, p1[u]);
            }
        }
    }

#pragma unroll
    for (int vi = 0; vi < VPT; ++vi) {
        const int n = n0 + v_t * VPT + vi;
        float* op = out + ((size_t)b * N + n) * Co + co0;
#pragma unroll
        for (int u = 0; u < NU; u += 2) {
            float2 r01 = unpk(acc[vi][u]);
            float2 r23 = unpk(acc[vi][u + 1]);
            float4 o = make_float4(r01.x, r01.y, r23.x, r23.y);
            if (RELU) {
                o.x = fmaxf(o.x, 0.f); o.y = fmaxf(o.y, 0.f);
                o.z = fmaxf(o.z, 0.f); o.w = fmaxf(o.w, 0.f);
            }
            *reinterpret_cast<float4*>(op + u * 2) = o;
        }
    }
}

// ---------------- head: Ci=64 -> Co=3, no relu -----------------------------
__global__ void __launch_bounds__(256)
k_head(const float* __restrict__ x, const int* __restrict__ idx,
       const float* __restrict__ dw, const float* __restrict__ pw,
       float* __restrict__ out, int N)
{
    constexpr int Ci = 64;
    constexpr int VT = 32;
    __shared__ float y_s[VT][Ci];
    __shared__ float pw_s[Ci * 3];
    __shared__ int idx_s[VT * SP];
    const int b = blockIdx.y, n0 = blockIdx.x * VT, tid = threadIdx.x;

    if (tid < Ci * 3) pw_s[tid] = pw[tid];
    for (int t = tid; t < VT * SP; t += 256)
        idx_s[t] = idx[(size_t)(n0 + t / SP) * SP + (t % SP)];
    __syncthreads();

    {
        const int ci = tid & (Ci - 1);
        const int vlo = (tid / Ci) * (VT / 4);
        float dwr[SP];
#pragma unroll
        for (int s = 0; s < SP; ++s) dwr[s] = __ldg(&dw[(size_t)ci * SP + s]);
        const float* xb = x + ((size_t)b * N) * Ci + ci;
#pragma unroll 2
        for (int v = vlo; v < vlo + VT / 4; ++v) {
            float acc = 0.f;
#pragma unroll
            for (int s = 0; s < SP; ++s)
                acc = fmaf(xb[(size_t)idx_s[v * SP + s] * Ci], dwr[s], acc);
            y_s[v][ci] = acc;
        }
    }
    __syncthreads();

    if (tid < VT * 3) {
        const int v = tid / 3, co = tid % 3;
        float acc = 0.f;
#pragma unroll
        for (int ci = 0; ci < Ci; ++ci)
            acc = fmaf(y_s[v][ci], pw_s[ci * 3 + co], acc);
        out[((size_t)b * N + n0 + v) * 3 + co] = acc;
    }
}

// ---------------------------------------------------------------------------
extern "C" void kernel_launch(void* const* d_in, const int* in_sizes, int n_in,
                              void* d_out, int out_size)
{
    const float* uv   = (const float*)d_in[0];
    const float* feat = (const float*)d_in[1];
    const float* up   = (const float*)d_in[2];
    const float* dw0  = (const float*)d_in[3];
    const float* pw0  = (const float*)d_in[4];
    const float* dw1  = (const float*)d_in[5];
    const float* pw1  = (const float*)d_in[6];
    const float* dw2  = (const float*)d_in[7];
    const float* pw2  = (const float*)d_in[8];
    const float* dw3  = (const float*)d_in[9];
    const float* pw3  = (const float*)d_in[10];
    const float* dwh  = (const float*)d_in[11];
    const float* pwh  = (const float*)d_in[12];

    // Resolve input ordering ambiguity via element counts.
    const float *upv0, *upv1, *upv2, *upv3;
    const int *spi0, *spi1, *spi2, *spi3, *upc0, *upc1, *upc2, *upc3;
    if (in_sizes[13] == 37632) {
        upv0 = (const float*)d_in[13]; upv1 = (const float*)d_in[14];
        upv2 = (const float*)d_in[15]; upv3 = (const float*)d_in[16];
        spi0 = (const int*)d_in[17]; spi1 = (const int*)d_in[18];
        spi2 = (const int*)d_in[19]; spi3 = (const int*)d_in[20];
        upc0 = (const int*)d_in[21]; upc1 = (const int*)d_in[22];
        upc2 = (const int*)d_in[23]; upc3 = (const int*)d_in[24];
    } else {
        spi0 = (const int*)d_in[13]; upc0 = (const int*)d_in[14]; upv0 = (const float*)d_in[15];
        spi1 = (const int*)d_in[16]; upc1 = (const int*)d_in[17]; upv1 = (const float*)d_in[18];
        spi2 = (const int*)d_in[19]; upc2 = (const int*)d_in[20]; upv2 = (const float*)d_in[21];
        spi3 = (const int*)d_in[22]; upc3 = (const int*)d_in[23]; upv3 = (const float*)d_in[24];
    }

    float *gsP, *bufA, *bufB;
    cudaGetSymbolAddress((void**)&gsP, g_gs);
    cudaGetSymbolAddress((void**)&bufA, g_bufA);
    cudaGetSymbolAddress((void**)&bufB, g_bufB);
    float* outp = (float*)d_out;

    // 1) grid sample -> gs (b,64,256)
    k_gridsample<<<B, 256>>>(uv, feat, gsP);
    // 2) upsample GEMM -> bufB (b,784,256)
    k_upsample<<<dim3(49, B), 256>>>(up, gsP, bufB);

    // stage 0: pool 784->1568 (col_3/val_3), dsconv idx_3 dw0/pw0 (256->256)
    k_pool<256><<<dim3(1568 / 4, B), 256>>>((const float4*)bufB, upc3, upv3,
                                            (float4*)bufA, 784, 1568);
    k_dsconv<256, 256, 32, 4, true>
        <<<dim3(1568 / 32, B), 256>>>(bufA, spi3, dw0, pw0, bufB, 1568);

    // stage 1: pool 1568->3136, dsconv idx_2 dw1/pw1 (256->256)
    k_pool<256><<<dim3(3136 / 4, B), 256>>>((const float4*)bufB, upc2, upv2,
                                            (float4*)bufA, 1568, 3136);
    k_dsconv<256, 256, 32, 4, true>
        <<<dim3(3136 / 32, B), 256>>>(bufA, spi2, dw1, pw1, bufB, 3136);

    // stage 2: pool 3136->6272, dsconv idx_1 dw2/pw2 (256->128)
    k_pool<256><<<dim3(6272 / 4, B), 256>>>((const float4*)bufB, upc1, upv1,
                                            (float4*)bufA, 3136, 6272);
    k_dsconv<256, 128, 32, 4, true>
        <<<dim3(6272 / 32, B), 256>>>(bufA, spi1, dw2, pw2, bufB, 6272);

    // stage 3: pool 6272->12544 (Ci=128), dsconv idx_0 dw3/pw3 (128->64)
    k_pool<128><<<dim3(12544 / 8, B), 256>>>((const float4*)bufB, upc0, upv0,
                                             (float4*)bufA, 6272, 12544);
    k_dsconv<128, 64, 64, 8, true>
        <<<dim3(12544 / 64, B), 256>>>(bufA, spi0, dw3, pw3, bufB, 12544);

    // head: Ci=64 -> 3, no relu
    k_head<<<dim3(12544 / 32, B), 256>>>(bufB, spi0, dwh, pwh, outp, 12544);
}

// round 4
// speedup vs baseline: 1.1101x; 1.1101x over previous
#include <cuda_runtime.h>
#include <cstddef>

// ---------------------------------------------------------------------------
// DWReg2DDecode3D: grid_sample -> upsample GEMM -> 4x(pool -> spiral dsconv
// -> relu) -> head dsconv.  B=16, NV={12544,6272,3136,1568,784}, SPIRAL=9.
// ---------------------------------------------------------------------------

#define B 16
#define SP 9

typedef unsigned long long ull;

// scratch (device globals; no allocations allowed)
__device__ float g_gs[B * 64 * 256];          // grid-sampled feats (b,p,c)
__device__ float g_bufB[12845056];            // conv outputs       (max 16*3136*256)
__device__ float g_bufA[25690112];            // pool outputs       (max 16*6272*256)

// ---------------- packed f32x2 helpers (sm_10x FFMA2 path) -----------------
__device__ __forceinline__ void fma2(ull& d, ull a, ull b) {
    asm("fma.rn.f32x2 %0, %1, %2, %0;" : "+l"(d) : "l"(a), "l"(b));
}
__device__ __forceinline__ ull dup2(float x) {
    ull u;
    asm("mov.b64 %0, {%1, %1};" : "=l"(u) : "f"(x));
    return u;
}
__device__ __forceinline__ ull pack2(float a, float b) {
    ull u;
    asm("mov.b64 %0, {%1, %2};" : "=l"(u) : "f"(a), "f"(b));
    return u;
}
__device__ __forceinline__ float2 unpk(ull u) {
    float2 r;
    asm("mov.b64 {%0, %1}, %2;" : "=f"(r.x), "=f"(r.y) : "l"(u));
    return r;
}

// ---------------- grid sample (bilinear, align_corners, zero pad) ----------
__global__ void __launch_bounds__(256)
k_gridsample(const float* __restrict__ uv, const float* __restrict__ feat,
             float* __restrict__ gs)
{
    const int b = blockIdx.x, c = threadIdx.x;
    const float* fb = feat + ((size_t)b * 256 + c) * 16;
    for (int p = 0; p < 64; ++p) {
        float gx = (uv[((size_t)b * 64 + p) * 2 + 0] - 0.5f) * 2.f;
        float gy = (uv[((size_t)b * 64 + p) * 2 + 1] - 0.5f) * 2.f;
        gx = fminf(fmaxf(gx, -1.f), 1.f);
        gy = fminf(fmaxf(gy, -1.f), 1.f);
        float x = (gx + 1.f) * 0.5f * 3.f;
        float y = (gy + 1.f) * 0.5f * 3.f;
        float x0f = floorf(x), y0f = floorf(y);
        int x0 = (int)x0f, y0 = (int)y0f;
        int x1 = x0 + 1, y1 = y0 + 1;
        float fx = x - x0f, fy = y - y0f;
        float wa = (1.f - fx) * (1.f - fy);
        float wb = (1.f - fx) * fy;
        float wc = fx * (1.f - fy);
        float wd = fx * fy;
        float Ia = (x0 >= 0 && x0 < 4 && y0 >= 0 && y0 < 4) ? fb[y0 * 4 + x0] : 0.f;
        float Ib = (x0 >= 0 && x0 < 4 && y1 >= 0 && y1 < 4) ? fb[y1 * 4 + x0] : 0.f;
        float Ic = (x1 >= 0 && x1 < 4 && y0 >= 0 && y0 < 4) ? fb[y0 * 4 + x1] : 0.f;
        float Id = (x1 >= 0 && x1 < 4 && y1 >= 0 && y1 < 4) ? fb[y1 * 4 + x1] : 0.f;
        gs[((size_t)b * 64 + p) * 256 + c] = Ia * wa + Ib * wb + Ic * wc + Id * wd;
    }
}

// ---------------- upsample GEMM: out[b,v,c] = sum_p up[v,p]*gs[b,p,c] ------
__global__ void __launch_bounds__(256)
k_upsample(const float* __restrict__ up, const float* __restrict__ gs,
           float* __restrict__ out)
{
    constexpr int VT = 16;
    __shared__ float up_s[VT][64];
    const int b = blockIdx.y, v0 = blockIdx.x * VT, c = threadIdx.x;
    for (int t = threadIdx.x; t < VT * 64; t += 256)
        up_s[t / 64][t % 64] = up[(size_t)(v0 + t / 64) * 64 + (t % 64)];
    __syncthreads();
    float acc[VT];
#pragma unroll
    for (int i = 0; i < VT; ++i) acc[i] = 0.f;
    for (int p = 0; p < 64; ++p) {
        float g = gs[((size_t)b * 64 + p) * 256 + c];
#pragma unroll
        for (int i = 0; i < VT; ++i) acc[i] = fmaf(up_s[i][p], g, acc[i]);
    }
#pragma unroll
    for (int i = 0; i < VT; ++i)
        out[((size_t)b * 784 + v0 + i) * 256 + c] = acc[i];
}

// ---------------- mesh up-pool: out[b,n,c] = sum_k x[b,col[3n+k],c]*val ----
template <int Ci>
__global__ void __launch_bounds__(256)
k_pool(const float4* __restrict__ x, const int* __restrict__ col,
       const float* __restrict__ val, float4* __restrict__ out,
       int Nin, int Nout)
{
    constexpr int CQ = Ci / 4;
    constexpr int VPB = 256 / CQ;
    const int b = blockIdx.y;
    const int n = blockIdx.x * VPB + threadIdx.x / CQ;
    const int cq = threadIdx.x % CQ;
    if (n >= Nout) return;
    const int c0 = col[3 * n + 0], c1 = col[3 * n + 1], c2 = col[3 * n + 2];
    const float v0 = val[3 * n + 0], v1 = val[3 * n + 1], v2 = val[3 * n + 2];
    const float4* xb = x + (size_t)b * Nin * CQ;
    float4 a = xb[(size_t)c0 * CQ + cq];
    float4 bb = xb[(size_t)c1 * CQ + cq];
    float4 cc = xb[(size_t)c2 * CQ + cq];
    float4 r;
    r.x = a.x * v0 + bb.x * v1 + cc.x * v2;
    r.y = a.y * v0 + bb.y * v1 + cc.y * v2;
    r.z = a.z * v0 + bb.z * v1 + cc.z * v2;
    r.w = a.w * v0 + bb.w * v1 + cc.w * v2;
    out[((size_t)b * Nout + n) * CQ + cq] = r;
}

// ---------------- fused spiral dsconv: gather*dw then @pw (+relu) ----------
// Phase A: y_s[v][ci] = sum_s x[idx[v,s], ci]*dw[ci,s]   (coalesced gathers)
// Phase B: SGEMM-style: pw staged per-KK-chunk in smem as pre-paired f32x2
// (co, co+32); acc[v][co-pair] register tile; y via broadcast LDS.64.
// Thread map phase B: lane = co-lane (32), warp = v-group (8 warps).
template <int Ci, int Co, int VT, bool RELU>
__global__ void __launch_bounds__(256, 2)
k_dsconv(const float* __restrict__ x, const int* __restrict__ idx,
         const float* __restrict__ dw, const float* __restrict__ pw,
         float* __restrict__ out, int N)
{
    constexpr int KK = 32;                 // k-chunk
    constexpr int NP = Co / 64;            // co-pairs per thread
    constexpr int VPT = VT / 8;            // vertices per thread (per warp-group)
    constexpr int CHP = Co / 2;            // pairs per pw row

    extern __shared__ __align__(16) char sm[];
    float* y_s  = reinterpret_cast<float*>(sm);                    // VT*Ci
    ull*   pwp  = reinterpret_cast<ull*>(sm + VT * Ci * 4);        // KK*CHP
    int*   idx_s = reinterpret_cast<int*>(sm + VT * Ci * 4 + KK * CHP * 8);

    const int b = blockIdx.y;
    const int n0 = blockIdx.x * VT;
    const int tid = threadIdx.x;

    for (int t = tid; t < VT * SP; t += 256)
        idx_s[t] = idx[(size_t)n0 * SP + t];
    __syncthreads();

    // ---- phase A ----
    {
        constexpr int CREP = 256 / Ci;
        constexpr int VCH = VT / CREP;
        const int ci = tid % Ci;
        const int vlo = (tid / Ci) * VCH;
        float dwr[SP];
#pragma unroll
        for (int s = 0; s < SP; ++s) dwr[s] = __ldg(&dw[(size_t)ci * SP + s]);
        const float* xb = x + ((size_t)b * N) * Ci + ci;
        for (int v = vlo; v < vlo + VCH; v += 2) {
            float a0 = 0.f, a1 = 0.f;
#pragma unroll
            for (int s = 0; s < SP; ++s) {
                a0 = fmaf(xb[(size_t)idx_s[v * SP + s] * Ci], dwr[s], a0);
                a1 = fmaf(xb[(size_t)idx_s[(v + 1) * SP + s] * Ci], dwr[s], a1);
            }
            y_s[(size_t)v * Ci + ci] = a0;
            y_s[(size_t)(v + 1) * Ci + ci] = a1;
        }
    }

    // ---- phase B ----
    const int lane = tid & 31;
    const int w = tid >> 5;

    ull acc[VPT][NP];
#pragma unroll
    for (int i = 0; i < VPT; ++i)
#pragma unroll
        for (int j = 0; j < NP; ++j) acc[i][j] = 0ull;

    const float* yrow = y_s + (size_t)(w * VPT) * Ci;

    for (int kc = 0; kc < Ci; kc += KK) {
        __syncthreads();   // y ready (1st iter) / prev pwp consumed
        for (int i = tid; i < KK * CHP; i += 256) {
            const int k = i / CHP;
            const int p = i - k * CHP;
            const int j = p >> 5, l = p & 31;
            const float* pr = pw + (size_t)(kc + k) * Co + j * 64 + l;
            pwp[(size_t)k * CHP + (j << 5) + l] = pack2(pr[0], pr[32]);
        }
        __syncthreads();
#pragma unroll 4
        for (int k = 0; k < KK; k += 2) {
            ull pA[NP], pB[NP];
#pragma unroll
            for (int j = 0; j < NP; ++j) {
                pA[j] = pwp[(size_t)k * CHP + (j << 5) + lane];
                pB[j] = pwp[(size_t)(k + 1) * CHP + (j << 5) + lane];
            }
#pragma unroll
            for (int vi = 0; vi < VPT; ++vi) {
                const float2 y2 = *reinterpret_cast<const float2*>(
                    yrow + (size_t)vi * Ci + kc + k);
                const ull ya = dup2(y2.x);
                const ull yb = dup2(y2.y);
#pragma unroll
                for (int j = 0; j < NP; ++j) {
                    fma2(acc[vi][j], ya, pA[j]);
                    fma2(acc[vi][j], yb, pB[j]);
                }
            }
        }
    }

#pragma unroll
    for (int vi = 0; vi < VPT; ++vi) {
        const int n = n0 + w * VPT + vi;
        float* op = out + ((size_t)b * N + n) * Co;
#pragma unroll
        for (int j = 0; j < NP; ++j) {
            float2 r = unpk(acc[vi][j]);
            if (RELU) { r.x = fmaxf(r.x, 0.f); r.y = fmaxf(r.y, 0.f); }
            op[j * 64 + lane] = r.x;
            op[j * 64 + 32 + lane] = r.y;
        }
    }
}

// ---------------- head: Ci=64 -> Co=3, no relu -----------------------------
__global__ void __launch_bounds__(256)
k_head(const float* __restrict__ x, const int* __restrict__ idx,
       const float* __restrict__ dw, const float* __restrict__ pw,
       float* __restrict__ out, int N)
{
    constexpr int Ci = 64;
    constexpr int VT = 32;
    __shared__ float y_s[VT][Ci];
    __shared__ float pw_s[Ci * 3];
    __shared__ int idx_s[VT * SP];
    const int b = blockIdx.y, n0 = blockIdx.x * VT, tid = threadIdx.x;

    if (tid < Ci * 3) pw_s[tid] = pw[tid];
    for (int t = tid; t < VT * SP; t += 256)
        idx_s[t] = idx[(size_t)n0 * SP + t];
    __syncthreads();

    {
        const int ci = tid & (Ci - 1);
        const int vlo = (tid / Ci) * (VT / 4);
        float dwr[SP];
#pragma unroll
        for (int s = 0; s < SP; ++s) dwr[s] = __ldg(&dw[(size_t)ci * SP + s]);
        const float* xb = x + ((size_t)b * N) * Ci + ci;
#pragma unroll 2
        for (int v = vlo; v < vlo + VT / 4; ++v) {
            float acc = 0.f;
#pragma unroll
            for (int s = 0; s < SP; ++s)
                acc = fmaf(xb[(size_t)idx_s[v * SP + s] * Ci], dwr[s], acc);
            y_s[v][ci] = acc;
        }
    }
    __syncthreads();

    if (tid < VT * 3) {
        const int v = tid / 3, co = tid % 3;
        float acc = 0.f;
#pragma unroll
        for (int ci = 0; ci < Ci; ++ci)
            acc = fmaf(y_s[v][ci], pw_s[ci * 3 + co], acc);
        out[((size_t)b * N + n0 + v) * 3 + co] = acc;
    }
}

// ---------------------------------------------------------------------------
extern "C" void kernel_launch(void* const* d_in, const int* in_sizes, int n_in,
                              void* d_out, int out_size)
{
    const float* uv   = (const float*)d_in[0];
    const float* feat = (const float*)d_in[1];
    const float* up   = (const float*)d_in[2];
    const float* dw0  = (const float*)d_in[3];
    const float* pw0  = (const float*)d_in[4];
    const float* dw1  = (const float*)d_in[5];
    const float* pw1  = (const float*)d_in[6];
    const float* dw2  = (const float*)d_in[7];
    const float* pw2  = (const float*)d_in[8];
    const float* dw3  = (const float*)d_in[9];
    const float* pw3  = (const float*)d_in[10];
    const float* dwh  = (const float*)d_in[11];
    const float* pwh  = (const float*)d_in[12];

    // Resolve input ordering ambiguity via element counts.
    const float *upv0, *upv1, *upv2, *upv3;
    const int *spi0, *spi1, *spi2, *spi3, *upc0, *upc1, *upc2, *upc3;
    if (in_sizes[13] == 37632) {
        upv0 = (const float*)d_in[13]; upv1 = (const float*)d_in[14];
        upv2 = (const float*)d_in[15]; upv3 = (const float*)d_in[16];
        spi0 = (const int*)d_in[17]; spi1 = (const int*)d_in[18];
        spi2 = (const int*)d_in[19]; spi3 = (const int*)d_in[20];
        upc0 = (const int*)d_in[21]; upc1 = (const int*)d_in[22];
        upc2 = (const int*)d_in[23]; upc3 = (const int*)d_in[24];
    } else {
        spi0 = (const int*)d_in[13]; upc0 = (const int*)d_in[14]; upv0 = (const float*)d_in[15];
        spi1 = (const int*)d_in[16]; upc1 = (const int*)d_in[17]; upv1 = (const float*)d_in[18];
        spi2 = (const int*)d_in[19]; upc2 = (const int*)d_in[20]; upv2 = (const float*)d_in[21];
        spi3 = (const int*)d_in[22]; upc3 = (const int*)d_in[23]; upv3 = (const float*)d_in[24];
    }

    float *gsP, *bufA, *bufB;
    cudaGetSymbolAddress((void**)&gsP, g_gs);
    cudaGetSymbolAddress((void**)&bufA, g_bufA);
    cudaGetSymbolAddress((void**)&bufB, g_bufB);
    float* outp = (float*)d_out;

    // dynamic smem sizes: y + pwp + idx
    constexpr int S0 = 32 * 256 * 4 + 32 * 128 * 8 + 32 * SP * 4;    // 66688
    constexpr int S1 = 64 * 256 * 4 + 32 * 128 * 8 + 64 * SP * 4;    // 100608
    constexpr int S2 = 64 * 256 * 4 + 32 * 64 * 8 + 64 * SP * 4;     // 84224
    constexpr int S3 = 128 * 128 * 4 + 32 * 32 * 8 + 128 * SP * 4;   // 78336
    cudaFuncSetAttribute(k_dsconv<256, 256, 32, true>,
                         cudaFuncAttributeMaxDynamicSharedMemorySize, S0);
    cudaFuncSetAttribute(k_dsconv<256, 256, 64, true>,
                         cudaFuncAttributeMaxDynamicSharedMemorySize, S1);
    cudaFuncSetAttribute(k_dsconv<256, 128, 64, true>,
                         cudaFuncAttributeMaxDynamicSharedMemorySize, S2);
    cudaFuncSetAttribute(k_dsconv<128, 64, 128, true>,
                         cudaFuncAttributeMaxDynamicSharedMemorySize, S3);

    // 1) grid sample -> gs (b,64,256)
    k_gridsample<<<B, 256>>>(uv, feat, gsP);
    // 2) upsample GEMM -> bufB (b,784,256)
    k_upsample<<<dim3(49, B), 256>>>(up, gsP, bufB);

    // stage 0: pool 784->1568 (col_3/val_3), dsconv idx_3 dw0/pw0 (256->256)
    k_pool<256><<<dim3(1568 / 4, B), 256>>>((const float4*)bufB, upc3, upv3,
                                            (float4*)bufA, 784, 1568);
    k_dsconv<256, 256, 32, true>
        <<<dim3(1568 / 32, B), 256, S0>>>(bufA, spi3, dw0, pw0, bufB, 1568);

    // stage 1: pool 1568->3136, dsconv idx_2 dw1/pw1 (256->256)
    k_pool<256><<<dim3(3136 / 4, B), 256>>>((const float4*)bufB, upc2, upv2,
                                            (float4*)bufA, 1568, 3136);
    k_dsconv<256, 256, 64, true>
        <<<dim3(3136 / 64, B), 256, S1>>>(bufA, spi2, dw1, pw1, bufB, 3136);

    // stage 2: pool 3136->6272, dsconv idx_1 dw2/pw2 (256->128)
    k_pool<256><<<dim3(6272 / 4, B), 256>>>((const float4*)bufB, upc1, upv1,
                                            (float4*)bufA, 3136, 6272);
    k_dsconv<256, 128, 64, true>
        <<<dim3(6272 / 64, B), 256, S2>>>(bufA, spi1, dw2, pw2, bufB, 6272);

    // stage 3: pool 6272->12544 (Ci=128), dsconv idx_0 dw3/pw3 (128->64)
    k_pool<128><<<dim3(12544 / 8, B), 256>>>((const float4*)bufB, upc0, upv0,
                                             (float4*)bufA, 6272, 12544);
    k_dsconv<128, 64, 128, true>
        <<<dim3(12544 / 128, B), 256, S3>>>(bufA, spi0, dw3, pw3, bufB, 12544);

    // head: Ci=64 -> 3, no relu
    k_head<<<dim3(12544 / 32, B), 256>>>(bufB, spi0, dwh, pwh, outp, 12544);
}

// round 5
// speedup vs baseline: 1.2588x; 1.1340x over previous
#include <cuda_runtime.h>
#include <cstddef>

// ---------------------------------------------------------------------------
// DWReg2DDecode3D: grid_sample -> upsample GEMM -> 4x(pool -> spiral gather
// -> GEMM+relu) -> head dsconv.  B=16, NV={12544,6272,3136,1568,784}, SP=9.
// Phase-split design: gather(+dw) and pointwise GEMM are separate kernels.
// ---------------------------------------------------------------------------

#define B 16
#define SP 9

typedef unsigned long long ull;

// scratch (device globals; no allocations allowed)
__device__ float g_gs[B * 64 * 256];          // grid-sampled feats
__device__ float g_bufB[12845056];            // conv outputs   (max 16*3136*256)
__device__ float g_bufA[25690112];            // pool outputs   (max 16*12544*128)
__device__ float g_bufC[25690112];            // gathered y     (same max)

// ---------------- packed f32x2 helpers (sm_10x FFMA2 path) -----------------
__device__ __forceinline__ void fma2(ull& d, ull a, ull b) {
    asm("fma.rn.f32x2 %0, %1, %2, %0;" : "+l"(d) : "l"(a), "l"(b));
}
__device__ __forceinline__ ull dup2(float x) {
    ull u;
    asm("mov.b64 %0, {%1, %1};" : "=l"(u) : "f"(x));
    return u;
}
__device__ __forceinline__ float2 unpk(ull u) {
    float2 r;
    asm("mov.b64 {%0, %1}, %2;" : "=f"(r.x), "=f"(r.y) : "l"(u));
    return r;
}

// ---------------- grid sample (bilinear, align_corners, zero pad) ----------
__global__ void __launch_bounds__(256)
k_gridsample(const float* __restrict__ uv, const float* __restrict__ feat,
             float* __restrict__ gs)
{
    const int b = blockIdx.x, c = threadIdx.x;
    const float* fb = feat + ((size_t)b * 256 + c) * 16;
    for (int p = 0; p < 64; ++p) {
        float gx = (uv[((size_t)b * 64 + p) * 2 + 0] - 0.5f) * 2.f;
        float gy = (uv[((size_t)b * 64 + p) * 2 + 1] - 0.5f) * 2.f;
        gx = fminf(fmaxf(gx, -1.f), 1.f);
        gy = fminf(fmaxf(gy, -1.f), 1.f);
        float x = (gx + 1.f) * 0.5f * 3.f;
        float y = (gy + 1.f) * 0.5f * 3.f;
        float x0f = floorf(x), y0f = floorf(y);
        int x0 = (int)x0f, y0 = (int)y0f;
        int x1 = x0 + 1, y1 = y0 + 1;
        float fx = x - x0f, fy = y - y0f;
        float wa = (1.f - fx) * (1.f - fy);
        float wb = (1.f - fx) * fy;
        float wc = fx * (1.f - fy);
        float wd = fx * fy;
        float Ia = (x0 >= 0 && x0 < 4 && y0 >= 0 && y0 < 4) ? fb[y0 * 4 + x0] : 0.f;
        float Ib = (x0 >= 0 && x0 < 4 && y1 >= 0 && y1 < 4) ? fb[y1 * 4 + x0] : 0.f;
        float Ic = (x1 >= 0 && x1 < 4 && y0 >= 0 && y0 < 4) ? fb[y0 * 4 + x1] : 0.f;
        float Id = (x1 >= 0 && x1 < 4 && y1 >= 0 && y1 < 4) ? fb[y1 * 4 + x1] : 0.f;
        gs[((size_t)b * 64 + p) * 256 + c] = Ia * wa + Ib * wb + Ic * wc + Id * wd;
    }
}

// ---------------- upsample GEMM: out[b,v,c] = sum_p up[v,p]*gs[b,p,c] ------
__global__ void __launch_bounds__(256)
k_upsample(const float* __restrict__ up, const float* __restrict__ gs,
           float* __restrict__ out)
{
    constexpr int VT = 16;
    __shared__ float up_s[VT][64];
    const int b = blockIdx.y, v0 = blockIdx.x * VT, c = threadIdx.x;
    for (int t = threadIdx.x; t < VT * 64; t += 256)
        up_s[t / 64][t % 64] = up[(size_t)(v0 + t / 64) * 64 + (t % 64)];
    __syncthreads();
    float acc[VT];
#pragma unroll
    for (int i = 0; i < VT; ++i) acc[i] = 0.f;
    for (int p = 0; p < 64; ++p) {
        float g = gs[((size_t)b * 64 + p) * 256 + c];
#pragma unroll
        for (int i = 0; i < VT; ++i) acc[i] = fmaf(up_s[i][p], g, acc[i]);
    }
#pragma unroll
    for (int i = 0; i < VT; ++i)
        out[((size_t)b * 784 + v0 + i) * 256 + c] = acc[i];
}

// ---------------- mesh up-pool: out[b,n,c] = sum_k x[b,col[3n+k],c]*val ----
template <int Ci>
__global__ void __launch_bounds__(256)
k_pool(const float4* __restrict__ x, const int* __restrict__ col,
       const float* __restrict__ val, float4* __restrict__ out,
       int Nin, int Nout)
{
    constexpr int CQ = Ci / 4;
    constexpr int VPB = 256 / CQ;
    const int b = blockIdx.y;
    const int n = blockIdx.x * VPB + threadIdx.x / CQ;
    const int cq = threadIdx.x % CQ;
    if (n >= Nout) return;
    const int c0 = col[3 * n + 0], c1 = col[3 * n + 1], c2 = col[3 * n + 2];
    const float v0 = val[3 * n + 0], v1 = val[3 * n + 1], v2 = val[3 * n + 2];
    const float4* xb = x + (size_t)b * Nin * CQ;
    float4 a = xb[(size_t)c0 * CQ + cq];
    float4 bb = xb[(size_t)c1 * CQ + cq];
    float4 cc = xb[(size_t)c2 * CQ + cq];
    float4 r;
    r.x = a.x * v0 + bb.x * v1 + cc.x * v2;
    r.y = a.y * v0 + bb.y * v1 + cc.y * v2;
    r.z = a.z * v0 + bb.z * v1 + cc.z * v2;
    r.w = a.w * v0 + bb.w * v1 + cc.w * v2;
    out[((size_t)b * Nout + n) * CQ + cq] = r;
}

// ---------------- spiral gather + depthwise: y[v][ci]=sum_s x[idx]*dw ------
template <int Ci>
__global__ void __launch_bounds__(256)
k_gather(const float* __restrict__ x, const int* __restrict__ idx,
         const float* __restrict__ dw, float* __restrict__ y, int N)
{
    constexpr int VT = 32;
    __shared__ int idx_s[VT * SP];
    const int b = blockIdx.y;
    const int n0 = blockIdx.x * VT;
    const int tid = threadIdx.x;

    for (int t = tid; t < VT * SP; t += 256)
        idx_s[t] = idx[(size_t)n0 * SP + t];
    __syncthreads();

    constexpr int CREP = 256 / Ci;
    constexpr int VCH = VT / CREP;
    const int ci = tid % Ci;
    const int vlo = (tid / Ci) * VCH;
    float dwr[SP];
#pragma unroll
    for (int s = 0; s < SP; ++s) dwr[s] = __ldg(&dw[(size_t)ci * SP + s]);
    const float* xb = x + ((size_t)b * N) * Ci + ci;
    float* yb = y + ((size_t)b * N + n0) * Ci + ci;
    for (int v = vlo; v < vlo + VCH; v += 2) {
        float a0 = 0.f, a1 = 0.f;
#pragma unroll
        for (int s = 0; s < SP; ++s) {
            a0 = fmaf(xb[(size_t)idx_s[v * SP + s] * Ci], dwr[s], a0);
            a1 = fmaf(xb[(size_t)idx_s[(v + 1) * SP + s] * Ci], dwr[s], a1);
        }
        yb[(size_t)v * Ci] = a0;
        yb[(size_t)(v + 1) * Ci] = a1;
    }
}

// ---------------- pointwise GEMM: C[M,Co] = relu(A[M,K] @ Bw[K,Co]) --------
// 256 threads; block tile TM x TN; thread tile VPT x 8 via f32x2 accs.
template <int K, int TM, int TN>
__global__ void __launch_bounds__(256, 2)
k_gemm(const float* __restrict__ A, const float* __restrict__ Bw,
       float* __restrict__ C, int Co)
{
    constexpr int KK = 16;
    constexpr int NC = K / KK;
    constexpr int AST = TM + 4;                  // padded As stride
    constexpr int TX = TN / 8;                   // threads along co
    constexpr int TY = 256 / TX;                 // threads along v
    constexpr int VPT = TM / TY;                 // v per thread (4 or 8)
    constexpr int AFR = VPT / 4;                 // a-frag float4s (1 or 2)
    constexpr int AF4 = TM * KK / 1024;          // per-thread A float4 loads
    constexpr int BF4 = TN * KK / 1024;          // per-thread B float4 loads
    static_assert(VPT == 4 || VPT == 8, "vpt");

    __shared__ float As[KK][AST];
    __shared__ float Bs[KK][TN];

    const int tid = threadIdx.x;
    const int m0 = blockIdx.x * TM;
    const int n0 = blockIdx.y * TN;
    const int tx = tid % TX;
    const int ty = tid / TX;

    float4 ar[AF4 > 0 ? AF4 : 1], br[BF4 > 0 ? BF4 : 1];

    auto loadA = [&](int kk) {
#pragma unroll
        for (int i = 0; i < AF4; ++i) {
            const int id = tid + i * 256;
            const int m = id >> 2, kq = id & 3;
            ar[i] = *reinterpret_cast<const float4*>(
                A + (size_t)(m0 + m) * K + kk + kq * 4);
        }
    };
    auto loadB = [&](int kk) {
#pragma unroll
        for (int i = 0; i < BF4; ++i) {
            const int id = tid + i * 256;
            const int r = id / (TN / 4), cq = id % (TN / 4);
            br[i] = *reinterpret_cast<const float4*>(
                Bw + (size_t)(kk + r) * Co + n0 + cq * 4);
        }
    };
    auto storeAB = [&]() {
#pragma unroll
        for (int i = 0; i < AF4; ++i) {
            const int id = tid + i * 256;
            const int m = id >> 2, kq = id & 3;
            As[kq * 4 + 0][m] = ar[i].x;
            As[kq * 4 + 1][m] = ar[i].y;
            As[kq * 4 + 2][m] = ar[i].z;
            As[kq * 4 + 3][m] = ar[i].w;
        }
#pragma unroll
        for (int i = 0; i < BF4; ++i) {
            const int id = tid + i * 256;
            const int r = id / (TN / 4), cq = id % (TN / 4);
            *reinterpret_cast<float4*>(&Bs[r][cq * 4]) = br[i];
        }
    };

    ull acc[VPT][4];
#pragma unroll
    for (int i = 0; i < VPT; ++i)
#pragma unroll
        for (int j = 0; j < 4; ++j) acc[i][j] = 0ull;

    loadA(0); loadB(0);
    for (int c = 0; c < NC; ++c) {
        __syncthreads();
        storeAB();
        __syncthreads();
        if (c + 1 < NC) { loadA((c + 1) * KK); loadB((c + 1) * KK); }
#pragma unroll
        for (int k = 0; k < KK; ++k) {
            float aa[VPT];
#pragma unroll
            for (int f = 0; f < AFR; ++f) {
                float4 av = *reinterpret_cast<const float4*>(
                    &As[k][f * (TM / 2) + ty * 4]);
                aa[f * 4 + 0] = av.x; aa[f * 4 + 1] = av.y;
                aa[f * 4 + 2] = av.z; aa[f * 4 + 3] = av.w;
            }
            ulonglong2 q0 = *reinterpret_cast<const ulonglong2*>(&Bs[k][tx * 4]);
            ulonglong2 q1 = *reinterpret_cast<const ulonglong2*>(
                &Bs[k][TN / 2 + tx * 4]);
#pragma unroll
            for (int vi = 0; vi < VPT; ++vi) {
                const ull ya = dup2(aa[vi]);
                fma2(acc[vi][0], ya, q0.x);
                fma2(acc[vi][1], ya, q0.y);
                fma2(acc[vi][2], ya, q1.x);
                fma2(acc[vi][3], ya, q1.y);
            }
        }
    }

#pragma unroll
    for (int vi = 0; vi < VPT; ++vi) {
        const int m = m0 + (vi / 4) * (TM / 2) + ty * 4 + (vi & 3);
        float* op = C + (size_t)m * Co + n0;
        float2 r0 = unpk(acc[vi][0]);
        float2 r1 = unpk(acc[vi][1]);
        float2 r2 = unpk(acc[vi][2]);
        float2 r3 = unpk(acc[vi][3]);
        float4 o0 = make_float4(fmaxf(r0.x, 0.f), fmaxf(r0.y, 0.f),
                                fmaxf(r1.x, 0.f), fmaxf(r1.y, 0.f));
        float4 o1 = make_float4(fmaxf(r2.x, 0.f), fmaxf(r2.y, 0.f),
                                fmaxf(r3.x, 0.f), fmaxf(r3.y, 0.f));
        *reinterpret_cast<float4*>(op + tx * 4) = o0;
        *reinterpret_cast<float4*>(op + TN / 2 + tx * 4) = o1;
    }
}

// ---------------- head: Ci=64 -> Co=3, no relu -----------------------------
__global__ void __launch_bounds__(256)
k_head(const float* __restrict__ x, const int* __restrict__ idx,
       const float* __restrict__ dw, const float* __restrict__ pw,
       float* __restrict__ out, int N)
{
    constexpr int Ci = 64;
    constexpr int VT = 32;
    __shared__ float y_s[VT][Ci];
    __shared__ float pw_s[Ci * 3];
    __shared__ int idx_s[VT * SP];
    const int b = blockIdx.y, n0 = blockIdx.x * VT, tid = threadIdx.x;

    if (tid < Ci * 3) pw_s[tid] = pw[tid];
    for (int t = tid; t < VT * SP; t += 256)
        idx_s[t] = idx[(size_t)n0 * SP + t];
    __syncthreads();

    {
        const int ci = tid & (Ci - 1);
        const int vlo = (tid / Ci) * (VT / 4);
        float dwr[SP];
#pragma unroll
        for (int s = 0; s < SP; ++s) dwr[s] = __ldg(&dw[(size_t)ci * SP + s]);
        const float* xb = x + ((size_t)b * N) * Ci + ci;
#pragma unroll 2
        for (int v = vlo; v < vlo + VT / 4; ++v) {
            float acc = 0.f;
#pragma unroll
            for (int s = 0; s < SP; ++s)
                acc = fmaf(xb[(size_t)idx_s[v * SP + s] * Ci], dwr[s], acc);
            y_s[v][ci] = acc;
        }
    }
    __syncthreads();

    if (tid < VT * 3) {
        const int v = tid / 3, co = tid % 3;
        float acc = 0.f;
#pragma unroll
        for (int ci = 0; ci < Ci; ++ci)
            acc = fmaf(y_s[v][ci], pw_s[ci * 3 + co], acc);
        out[((size_t)b * N + n0 + v) * 3 + co] = acc;
    }
}

// ---------------------------------------------------------------------------
extern "C" void kernel_launch(void* const* d_in, const int* in_sizes, int n_in,
                              void* d_out, int out_size)
{
    const float* uv   = (const float*)d_in[0];
    const float* feat = (const float*)d_in[1];
    const float* up   = (const float*)d_in[2];
    const float* dw0  = (const float*)d_in[3];
    const float* pw0  = (const float*)d_in[4];
    const float* dw1  = (const float*)d_in[5];
    const float* pw1  = (const float*)d_in[6];
    const float* dw2  = (const float*)d_in[7];
    const float* pw2  = (const float*)d_in[8];
    const float* dw3  = (const float*)d_in[9];
    const float* pw3  = (const float*)d_in[10];
    const float* dwh  = (const float*)d_in[11];
    const float* pwh  = (const float*)d_in[12];

    // Resolve input ordering ambiguity via element counts.
    const float *upv0, *upv1, *upv2, *upv3;
    const int *spi0, *spi1, *spi2, *spi3, *upc0, *upc1, *upc2, *upc3;
    if (in_sizes[13] == 37632) {
        upv0 = (const float*)d_in[13]; upv1 = (const float*)d_in[14];
        upv2 = (const float*)d_in[15]; upv3 = (const float*)d_in[16];
        spi0 = (const int*)d_in[17]; spi1 = (const int*)d_in[18];
        spi2 = (const int*)d_in[19]; spi3 = (const int*)d_in[20];
        upc0 = (const int*)d_in[21]; upc1 = (const int*)d_in[22];
        upc2 = (const int*)d_in[23]; upc3 = (const int*)d_in[24];
    } else {
        spi0 = (const int*)d_in[13]; upc0 = (const int*)d_in[14]; upv0 = (const float*)d_in[15];
        spi1 = (const int*)d_in[16]; upc1 = (const int*)d_in[17]; upv1 = (const float*)d_in[18];
        spi2 = (const int*)d_in[19]; upc2 = (const int*)d_in[20]; upv2 = (const float*)d_in[21];
        spi3 = (const int*)d_in[22]; upc3 = (const int*)d_in[23]; upv3 = (const float*)d_in[24];
    }

    float *gsP, *bufA, *bufB, *bufC;
    cudaGetSymbolAddress((void**)&gsP, g_gs);
    cudaGetSymbolAddress((void**)&bufA, g_bufA);
    cudaGetSymbolAddress((void**)&bufB, g_bufB);
    cudaGetSymbolAddress((void**)&bufC, g_bufC);
    float* outp = (float*)d_out;

    // 1) grid sample -> gs (b,64,256)
    k_gridsample<<<B, 256>>>(uv, feat, gsP);
    // 2) upsample GEMM -> bufB (b,784,256)
    k_upsample<<<dim3(49, B), 256>>>(up, gsP, bufB);

    // stage 0: pool 784->1568, gather idx_3, GEMM 256->256 (dw0/pw0)
    k_pool<256><<<dim3(1568 / 4, B), 256>>>((const float4*)bufB, upc3, upv3,
                                            (float4*)bufA, 784, 1568);
    k_gather<256><<<dim3(1568 / 32, B), 256>>>(bufA, spi3, dw0, bufC, 1568);
    k_gemm<256, 64, 128><<<dim3(B * 1568 / 64, 2), 256>>>(bufC, pw0, bufB, 256);

    // stage 1: pool 1568->3136, gather idx_2, GEMM 256->256 (dw1/pw1)
    k_pool<256><<<dim3(3136 / 4, B), 256>>>((const float4*)bufB, upc2, upv2,
                                            (float4*)bufA, 1568, 3136);
    k_gather<256><<<dim3(3136 / 32, B), 256>>>(bufA, spi2, dw1, bufC, 3136);
    k_gemm<256, 128, 128><<<dim3(B * 3136 / 128, 2), 256>>>(bufC, pw1, bufB, 256);

    // stage 2: pool 3136->6272, gather idx_1, GEMM 256->128 (dw2/pw2)
    k_pool<256><<<dim3(6272 / 4, B), 256>>>((const float4*)bufB, upc1, upv1,
                                            (float4*)bufA, 3136, 6272);
    k_gather<256><<<dim3(6272 / 32, B), 256>>>(bufA, spi1, dw2, bufC, 6272);
    k_gemm<256, 128, 128><<<dim3(B * 6272 / 128, 1), 256>>>(bufC, pw2, bufB, 128);

    // stage 3: pool 6272->12544 (Ci=128), gather idx_0, GEMM 128->64 (dw3/pw3)
    k_pool<128><<<dim3(12544 / 8, B), 256>>>((const float4*)bufB, upc0, upv0,
                                             (float4*)bufA, 6272, 12544);
    k_gather<128><<<dim3(12544 / 32, B), 256>>>(bufA, spi0, dw3, bufC, 12544);
    k_gemm<128, 256, 64><<<dim3(B * 12544 / 256, 1), 256>>>(bufC, pw3, bufB, 64);

    // head: Ci=64 -> 3, no relu
    k_head<<<dim3(12544 / 32, B), 256>>>(bufB, spi0, dwh, pwh, outp, 12544);
}

// round 6
// speedup vs baseline: 1.3241x; 1.0519x over previous
#include <cuda_runtime.h>
#include <cstddef>

// ---------------------------------------------------------------------------
// DWReg2DDecode3D: grid_sample -> upsample GEMM -> 4x(pool -> spiral gather
// -> GEMM+relu) -> head dsconv.  B=16, NV={12544,6272,3136,1568,784}, SP=9.
// Phase-split design: gather(+dw) and pointwise GEMM are separate kernels.
// ---------------------------------------------------------------------------

#define B 16
#define SP 9

typedef unsigned long long ull;

// scratch (device globals; no allocations allowed)
__device__ float g_gs[B * 64 * 256];          // grid-sampled feats
__device__ float g_bufB[12845056];            // conv outputs   (max 16*3136*256)
__device__ float g_bufA[25690112];            // pool outputs   (max 16*12544*128)
__device__ float g_bufC[25690112];            // gathered y     (same max)

// ---------------- packed f32x2 helpers (sm_10x FFMA2 path) -----------------
__device__ __forceinline__ void fma2(ull& d, ull a, ull b) {
    asm("fma.rn.f32x2 %0, %1, %2, %0;" : "+l"(d) : "l"(a), "l"(b));
}
__device__ __forceinline__ ull dup2(float x) {
    ull u;
    asm("mov.b64 %0, {%1, %1};" : "=l"(u) : "f"(x));
    return u;
}
__device__ __forceinline__ ull pack2(float a, float b) {
    ull u;
    asm("mov.b64 %0, {%1, %2};" : "=l"(u) : "f"(a), "f"(b));
    return u;
}
__device__ __forceinline__ float2 unpk(ull u) {
    float2 r;
    asm("mov.b64 {%0, %1}, %2;" : "=f"(r.x), "=f"(r.y) : "l"(u));
    return r;
}

// ---------------- grid sample (bilinear, align_corners, zero pad) ----------
__global__ void __launch_bounds__(256)
k_gridsample(const float* __restrict__ uv, const float* __restrict__ feat,
             float* __restrict__ gs)
{
    const int b = blockIdx.x, c = threadIdx.x;
    const float* fb = feat + ((size_t)b * 256 + c) * 16;
    for (int p = 0; p < 64; ++p) {
        float gx = (uv[((size_t)b * 64 + p) * 2 + 0] - 0.5f) * 2.f;
        float gy = (uv[((size_t)b * 64 + p) * 2 + 1] - 0.5f) * 2.f;
        gx = fminf(fmaxf(gx, -1.f), 1.f);
        gy = fminf(fmaxf(gy, -1.f), 1.f);
        float x = (gx + 1.f) * 0.5f * 3.f;
        float y = (gy + 1.f) * 0.5f * 3.f;
        float x0f = floorf(x), y0f = floorf(y);
        int x0 = (int)x0f, y0 = (int)y0f;
        int x1 = x0 + 1, y1 = y0 + 1;
        float fx = x - x0f, fy = y - y0f;
        float wa = (1.f - fx) * (1.f - fy);
        float wb = (1.f - fx) * fy;
        float wc = fx * (1.f - fy);
        float wd = fx * fy;
        float Ia = (x0 >= 0 && x0 < 4 && y0 >= 0 && y0 < 4) ? fb[y0 * 4 + x0] : 0.f;
        float Ib = (x0 >= 0 && x0 < 4 && y1 >= 0 && y1 < 4) ? fb[y1 * 4 + x0] : 0.f;
        float Ic = (x1 >= 0 && x1 < 4 && y0 >= 0 && y0 < 4) ? fb[y0 * 4 + x1] : 0.f;
        float Id = (x1 >= 0 && x1 < 4 && y1 >= 0 && y1 < 4) ? fb[y1 * 4 + x1] : 0.f;
        gs[((size_t)b * 64 + p) * 256 + c] = Ia * wa + Ib * wb + Ic * wc + Id * wd;
    }
}

// ---------------- upsample GEMM: out[b,v,c] = sum_p up[v,p]*gs[b,p,c] ------
__global__ void __launch_bounds__(256)
k_upsample(const float* __restrict__ up, const float* __restrict__ gs,
           float* __restrict__ out)
{
    constexpr int VT = 16;
    __shared__ float up_s[VT][64];
    const int b = blockIdx.y, v0 = blockIdx.x * VT, c = threadIdx.x;
    for (int t = threadIdx.x; t < VT * 64; t += 256)
        up_s[t / 64][t % 64] = up[(size_t)(v0 + t / 64) * 64 + (t % 64)];
    __syncthreads();
    float acc[VT];
#pragma unroll
    for (int i = 0; i < VT; ++i) acc[i] = 0.f;
    for (int p = 0; p < 64; ++p) {
        float g = gs[((size_t)b * 64 + p) * 256 + c];
#pragma unroll
        for (int i = 0; i < VT; ++i) acc[i] = fmaf(up_s[i][p], g, acc[i]);
    }
#pragma unroll
    for (int i = 0; i < VT; ++i)
        out[((size_t)b * 784 + v0 + i) * 256 + c] = acc[i];
}

// ---------------- mesh up-pool: out[b,n,c] = sum_k x[b,col[3n+k],c]*val ----
template <int Ci>
__global__ void __launch_bounds__(256)
k_pool(const float4* __restrict__ x, const int* __restrict__ col,
       const float* __restrict__ val, float4* __restrict__ out,
       int Nin, int Nout)
{
    constexpr int CQ = Ci / 4;
    constexpr int VPB = 256 / CQ;
    const int b = blockIdx.y;
    const int n = blockIdx.x * VPB + threadIdx.x / CQ;
    const int cq = threadIdx.x % CQ;
    if (n >= Nout) return;
    const int c0 = col[3 * n + 0], c1 = col[3 * n + 1], c2 = col[3 * n + 2];
    const float v0 = val[3 * n + 0], v1 = val[3 * n + 1], v2 = val[3 * n + 2];
    const float4* xb = x + (size_t)b * Nin * CQ;
    float4 a = xb[(size_t)c0 * CQ + cq];
    float4 bb = xb[(size_t)c1 * CQ + cq];
    float4 cc = xb[(size_t)c2 * CQ + cq];
    float4 r;
    r.x = a.x * v0 + bb.x * v1 + cc.x * v2;
    r.y = a.y * v0 + bb.y * v1 + cc.y * v2;
    r.z = a.z * v0 + bb.z * v1 + cc.z * v2;
    r.w = a.w * v0 + bb.w * v1 + cc.w * v2;
    out[((size_t)b * Nout + n) * CQ + cq] = r;
}

// ---------------- spiral gather + depthwise: y[v][ci]=sum_s x[idx]*dw ------
// LDG.128 gathers (4 ci/thread), packed-dw FFMA2, float4 stores.
template <int Ci>
__global__ void __launch_bounds__(256)
k_gather(const float* __restrict__ x, const int* __restrict__ idx,
         const float* __restrict__ dw, float* __restrict__ y, int N)
{
    constexpr int VT = 32;
    constexpr int TPV = Ci / 4;          // threads per vertex (64 or 32)
    constexpr int VG = 256 / TPV;        // concurrent vertex groups
    constexpr int VCH = VT / VG;         // vertices per thread
    __shared__ int idx_s[VT * SP];
    const int b = blockIdx.y;
    const int n0 = blockIdx.x * VT;
    const int tid = threadIdx.x;

    for (int t = tid; t < VT * SP; t += 256)
        idx_s[t] = idx[(size_t)n0 * SP + t];
    __syncthreads();

    const int cq = (tid % TPV) * 4;
    const int vlo = (tid / TPV) * VCH;

    ull dw01[SP], dw23[SP];
#pragma unroll
    for (int s = 0; s < SP; ++s) {
        dw01[s] = pack2(__ldg(&dw[(size_t)(cq + 0) * SP + s]),
                        __ldg(&dw[(size_t)(cq + 1) * SP + s]));
        dw23[s] = pack2(__ldg(&dw[(size_t)(cq + 2) * SP + s]),
                        __ldg(&dw[(size_t)(cq + 3) * SP + s]));
    }
    const float* xb = x + ((size_t)b * N) * Ci + cq;
    float* yb = y + ((size_t)b * N + n0) * Ci + cq;
#pragma unroll 2
    for (int v = vlo; v < vlo + VCH; ++v) {
        const int* iv = idx_s + v * SP;
        ull a01 = 0ull, a23 = 0ull;
#pragma unroll
        for (int s = 0; s < SP; ++s) {
            float4 xv = *reinterpret_cast<const float4*>(
                xb + (size_t)iv[s] * Ci);
            fma2(a01, pack2(xv.x, xv.y), dw01[s]);
            fma2(a23, pack2(xv.z, xv.w), dw23[s]);
        }
        float2 r01 = unpk(a01), r23 = unpk(a23);
        *reinterpret_cast<float4*>(yb + (size_t)v * Ci) =
            make_float4(r01.x, r01.y, r23.x, r23.y);
    }
}

// ---------------- pointwise GEMM: C[M,Co] = relu(A[M,K] @ Bw[K,Co]) --------
// 256 threads; block tile TM x TN; thread tile VPT x 8 via f32x2 accs.
template <int K, int TM, int TN>
__global__ void __launch_bounds__(256, 2)
k_gemm(const float* __restrict__ A, const float* __restrict__ Bw,
       float* __restrict__ C, int Co)
{
    constexpr int KK = 16;
    constexpr int NC = K / KK;
    constexpr int AST = TM + 4;                  // padded As stride
    constexpr int TX = TN / 8;                   // threads along co
    constexpr int TY = 256 / TX;                 // threads along v
    constexpr int VPT = TM / TY;                 // v per thread (4 or 8)
    constexpr int AFR = VPT / 4;                 // a-frag float4s (1 or 2)
    constexpr int AF4 = TM * KK / 1024;          // per-thread A float4 loads
    constexpr int BF4 = TN * KK / 1024;          // per-thread B float4 loads
    static_assert(VPT == 4 || VPT == 8, "vpt");

    __shared__ float As[KK][AST];
    __shared__ float Bs[KK][TN];

    const int tid = threadIdx.x;
    const int m0 = blockIdx.x * TM;
    const int n0 = blockIdx.y * TN;
    const int tx = tid % TX;
    const int ty = tid / TX;

    float4 ar[AF4 > 0 ? AF4 : 1], br[BF4 > 0 ? BF4 : 1];

    auto loadA = [&](int kk) {
#pragma unroll
        for (int i = 0; i < AF4; ++i) {
            const int id = tid + i * 256;
            const int m = id >> 2, kq = id & 3;
            ar[i] = *reinterpret_cast<const float4*>(
                A + (size_t)(m0 + m) * K + kk + kq * 4);
        }
    };
    auto loadB = [&](int kk) {
#pragma unroll
        for (int i = 0; i < BF4; ++i) {
            const int id = tid + i * 256;
            const int r = id / (TN / 4), cq = id % (TN / 4);
            br[i] = *reinterpret_cast<const float4*>(
                Bw + (size_t)(kk + r) * Co + n0 + cq * 4);
        }
    };
    auto storeAB = [&]() {
#pragma unroll
        for (int i = 0; i < AF4; ++i) {
            const int id = tid + i * 256;
            const int m = id >> 2, kq = id & 3;
            As[kq * 4 + 0][m] = ar[i].x;
            As[kq * 4 + 1][m] = ar[i].y;
            As[kq * 4 + 2][m] = ar[i].z;
            As[kq * 4 + 3][m] = ar[i].w;
        }
#pragma unroll
        for (int i = 0; i < BF4; ++i) {
            const int id = tid + i * 256;
            const int r = id / (TN / 4), cq = id % (TN / 4);
            *reinterpret_cast<float4*>(&Bs[r][cq * 4]) = br[i];
        }
    };

    ull acc[VPT][4];
#pragma unroll
    for (int i = 0; i < VPT; ++i)
#pragma unroll
        for (int j = 0; j < 4; ++j) acc[i][j] = 0ull;

    loadA(0); loadB(0);
    for (int c = 0; c < NC; ++c) {
        __syncthreads();
        storeAB();
        __syncthreads();
        if (c + 1 < NC) { loadA((c + 1) * KK); loadB((c + 1) * KK); }
#pragma unroll
        for (int k = 0; k < KK; ++k) {
            float aa[VPT];
#pragma unroll
            for (int f = 0; f < AFR; ++f) {
                float4 av = *reinterpret_cast<const float4*>(
                    &As[k][f * (TM / 2) + ty * 4]);
                aa[f * 4 + 0] = av.x; aa[f * 4 + 1] = av.y;
                aa[f * 4 + 2] = av.z; aa[f * 4 + 3] = av.w;
            }
            ulonglong2 q0 = *reinterpret_cast<const ulonglong2*>(&Bs[k][tx * 4]);
            ulonglong2 q1 = *reinterpret_cast<const ulonglong2*>(
                &Bs[k][TN / 2 + tx * 4]);
#pragma unroll
            for (int vi = 0; vi < VPT; ++vi) {
                const ull ya = dup2(aa[vi]);
                fma2(acc[vi][0], ya, q0.x);
                fma2(acc[vi][1], ya, q0.y);
                fma2(acc[vi][2], ya, q1.x);
                fma2(acc[vi][3], ya, q1.y);
            }
        }
    }

#pragma unroll
    for (int vi = 0; vi < VPT; ++vi) {
        const int m = m0 + (vi / 4) * (TM / 2) + ty * 4 + (vi & 3);
        float* op = C + (size_t)m * Co + n0;
        float2 r0 = unpk(acc[vi][0]);
        float2 r1 = unpk(acc[vi][1]);
        float2 r2 = unpk(acc[vi][2]);
        float2 r3 = unpk(acc[vi][3]);
        float4 o0 = make_float4(fmaxf(r0.x, 0.f), fmaxf(r0.y, 0.f),
                                fmaxf(r1.x, 0.f), fmaxf(r1.y, 0.f));
        float4 o1 = make_float4(fmaxf(r2.x, 0.f), fmaxf(r2.y, 0.f),
                                fmaxf(r3.x, 0.f), fmaxf(r3.y, 0.f));
        *reinterpret_cast<float4*>(op + tx * 4) = o0;
        *reinterpret_cast<float4*>(op + TN / 2 + tx * 4) = o1;
    }
}

// ---------------- head: Ci=64 -> Co=3, no relu -----------------------------
__global__ void __launch_bounds__(256)
k_head(const float* __restrict__ x, const int* __restrict__ idx,
       const float* __restrict__ dw, const float* __restrict__ pw,
       float* __restrict__ out, int N)
{
    constexpr int Ci = 64;
    constexpr int VT = 32;
    __shared__ float y_s[VT][Ci];
    __shared__ float pw_s[Ci * 3];
    __shared__ int idx_s[VT * SP];
    const int b = blockIdx.y, n0 = blockIdx.x * VT, tid = threadIdx.x;

    if (tid < Ci * 3) pw_s[tid] = pw[tid];
    for (int t = tid; t < VT * SP; t += 256)
        idx_s[t] = idx[(size_t)n0 * SP + t];
    __syncthreads();

    {
        const int ci = tid & (Ci - 1);
        const int vlo = (tid / Ci) * (VT / 4);
        float dwr[SP];
#pragma unroll
        for (int s = 0; s < SP; ++s) dwr[s] = __ldg(&dw[(size_t)ci * SP + s]);
        const float* xb = x + ((size_t)b * N) * Ci + ci;
#pragma unroll 2
        for (int v = vlo; v < vlo + VT / 4; ++v) {
            float acc = 0.f;
#pragma unroll
            for (int s = 0; s < SP; ++s)
                acc = fmaf(xb[(size_t)idx_s[v * SP + s] * Ci], dwr[s], acc);
            y_s[v][ci] = acc;
        }
    }
    __syncthreads();

    if (tid < VT * 3) {
        const int v = tid / 3, co = tid % 3;
        float acc = 0.f;
#pragma unroll
        for (int ci = 0; ci < Ci; ++ci)
            acc = fmaf(y_s[v][ci], pw_s[ci * 3 + co], acc);
        out[((size_t)b * N + n0 + v) * 3 + co] = acc;
    }
}

// ---------------------------------------------------------------------------
extern "C" void kernel_launch(void* const* d_in, const int* in_sizes, int n_in,
                              void* d_out, int out_size)
{
    const float* uv   = (const float*)d_in[0];
    const float* feat = (const float*)d_in[1];
    const float* up   = (const float*)d_in[2];
    const float* dw0  = (const float*)d_in[3];
    const float* pw0  = (const float*)d_in[4];
    const float* dw1  = (const float*)d_in[5];
    const float* pw1  = (const float*)d_in[6];
    const float* dw2  = (const float*)d_in[7];
    const float* pw2  = (const float*)d_in[8];
    const float* dw3  = (const float*)d_in[9];
    const float* pw3  = (const float*)d_in[10];
    const float* dwh  = (const float*)d_in[11];
    const float* pwh  = (const float*)d_in[12];

    // Resolve input ordering ambiguity via element counts.
    const float *upv0, *upv1, *upv2, *upv3;
    const int *spi0, *spi1, *spi2, *spi3, *upc0, *upc1, *upc2, *upc3;
    if (in_sizes[13] == 37632) {
        upv0 = (const float*)d_in[13]; upv1 = (const float*)d_in[14];
        upv2 = (const float*)d_in[15]; upv3 = (const float*)d_in[16];
        spi0 = (const int*)d_in[17]; spi1 = (const int*)d_in[18];
        spi2 = (const int*)d_in[19]; spi3 = (const int*)d_in[20];
        upc0 = (const int*)d_in[21]; upc1 = (const int*)d_in[22];
        upc2 = (const int*)d_in[23]; upc3 = (const int*)d_in[24];
    } else {
        spi0 = (const int*)d_in[13]; upc0 = (const int*)d_in[14]; upv0 = (const float*)d_in[15];
        spi1 = (const int*)d_in[16]; upc1 = (const int*)d_in[17]; upv1 = (const float*)d_in[18];
        spi2 = (const int*)d_in[19]; upc2 = (const int*)d_in[20]; upv2 = (const float*)d_in[21];
        spi3 = (const int*)d_in[22]; upc3 = (const int*)d_in[23]; upv3 = (const float*)d_in[24];
    }

    float *gsP, *bufA, *bufB, *bufC;
    cudaGetSymbolAddress((void**)&gsP, g_gs);
    cudaGetSymbolAddress((void**)&bufA, g_bufA);
    cudaGetSymbolAddress((void**)&bufB, g_bufB);
    cudaGetSymbolAddress((void**)&bufC, g_bufC);
    float* outp = (float*)d_out;

    // 1) grid sample -> gs (b,64,256)
    k_gridsample<<<B, 256>>>(uv, feat, gsP);
    // 2) upsample GEMM -> bufB (b,784,256)
    k_upsample<<<dim3(49, B), 256>>>(up, gsP, bufB);

    // stage 0: pool 784->1568, gather idx_3, GEMM 256->256 (dw0/pw0)
    k_pool<256><<<dim3(1568 / 4, B), 256>>>((const float4*)bufB, upc3, upv3,
                                            (float4*)bufA, 784, 1568);
    k_gather<256><<<dim3(1568 / 32, B), 256>>>(bufA, spi3, dw0, bufC, 1568);
    k_gemm<256, 64, 128><<<dim3(B * 1568 / 64, 2), 256>>>(bufC, pw0, bufB, 256);

    // stage 1: pool 1568->3136, gather idx_2, GEMM 256->256 (dw1/pw1)
    k_pool<256><<<dim3(3136 / 4, B), 256>>>((const float4*)bufB, upc2, upv2,
                                            (float4*)bufA, 1568, 3136);
    k_gather<256><<<dim3(3136 / 32, B), 256>>>(bufA, spi2, dw1, bufC, 3136);
    k_gemm<256, 128, 128><<<dim3(B * 3136 / 128, 2), 256>>>(bufC, pw1, bufB, 256);

    // stage 2: pool 3136->6272, gather idx_1, GEMM 256->128 (dw2/pw2)
    k_pool<256><<<dim3(6272 / 4, B), 256>>>((const float4*)bufB, upc1, upv1,
                                            (float4*)bufA, 3136, 6272);
    k_gather<256><<<dim3(6272 / 32, B), 256>>>(bufA, spi1, dw2, bufC, 6272);
    k_gemm<256, 128, 128><<<dim3(B * 6272 / 128, 1), 256>>>(bufC, pw2, bufB, 128);

    // stage 3: pool 6272->12544 (Ci=128), gather idx_0, GEMM 128->64 (dw3/pw3)
    k_pool<128><<<dim3(12544 / 8, B), 256>>>((const float4*)bufB, upc0, upv0,
                                             (float4*)bufA, 6272, 12544);
    k_gather<128><<<dim3(12544 / 32, B), 256>>>(bufA, spi0, dw3, bufC, 12544);
    k_gemm<128, 256, 64><<<dim3(B * 12544 / 256, 1), 256>>>(bufC, pw3, bufB, 64);

    // head: Ci=64 -> 3, no relu
    k_head<<<dim3(12544 / 32, B), 256>>>(bufB, spi0, dwh, pwh, outp, 12544);
}